// round 7
// baseline (speedup 1.0000x reference)
#include <cuda_runtime.h>
#include <math.h>

// Problem constants
#define BATCH  1024
#define NDIM   256
#define NENT   50000
#define ROWS   2048              // 2 matrices (head/tail) x 1024 rows
#define BM     128               // GEMM row tile
#define BE     128               // GEMM entity tile
#define NCB    ((NENT + BE - 1) / BE)   // 391 column blocks

// ---------------- device scratch (static: no allocation) ----------------
__device__ __align__(16) float g_mean[3 * NDIM];
__device__ __align__(16) float g_rstd[3 * NDIM];
__device__ __align__(16) float g_vec[ROWS * NDIM];        // 2 MB: head rows [0,1024), tail rows [1024,2048)
__device__ float g_zlab[ROWS];
__device__ float g_part[(size_t)ROWS * NCB * 4];          // 12.8 MB moment partials
__device__ float g_rowtot[ROWS];

// ---------------- K1: batch-norm statistics over the three gathers ----------------
// grid = 3*256 blocks (set, dim), 256 threads
__global__ void k_bn(const int* __restrict__ facts,
                     const float* __restrict__ ent_w,
                     const float* __restrict__ rel_w) {
    int s = blockIdx.x >> 8;       // 0: h->ent, 1: t->ent, 2: r->rel
    int d = blockIdx.x & 255;
    const float* tab = (s < 2) ? ent_w : rel_w;
    float sum = 0.f, sq = 0.f;
    for (int b = threadIdx.x; b < BATCH; b += 256) {
        int idx = facts[b * 3 + s];
        float x = tab[idx * NDIM + d];
        sum += x;
        sq  += x * x;
    }
    __shared__ float s1[256], s2[256];
    s1[threadIdx.x] = sum;
    s2[threadIdx.x] = sq;
    __syncthreads();
    for (int o = 128; o > 0; o >>= 1) {
        if (threadIdx.x < o) {
            s1[threadIdx.x] += s1[threadIdx.x + o];
            s2[threadIdx.x] += s2[threadIdx.x + o];
        }
        __syncthreads();
    }
    if (threadIdx.x == 0) {
        float m = s1[0] * (1.f / BATCH);
        float v = s2[0] * (1.f / BATCH) - m * m;   // biased variance (matches jnp.var)
        g_mean[s * NDIM + d] = m;
        g_rstd[s * NDIM + d] = rsqrtf(v + 1e-5f);
    }
}

// ---------------- K2: build head_vec / tail_vec via the alpha einsum ----------------
// grid = 1024 blocks (one per fact), 64 threads (one per l in [0,64))
__global__ void k_vec(const int* __restrict__ facts,
                      const float* __restrict__ ent_w,
                      const float* __restrict__ rel_w,
                      const float* __restrict__ bne_g, const float* __restrict__ bne_b,
                      const float* __restrict__ bnr_g, const float* __restrict__ bnr_b,
                      const int* __restrict__ arch) {
    int b = blockIdx.x;
    int l = threadIdx.x;
    __shared__ float af[64];
    int a = arch[l];
    af[l] = (a == 0) ? 0.f : ((a == 1) ? 1.f : -1.f);
    __syncthreads();

    int hI = facts[b * 3 + 0];
    int tI = facts[b * 3 + 1];
    int rI = facts[b * 3 + 2];

    float re[4], te[4], he[4];
#pragma unroll
    for (int i = 0; i < 4; i++) {
        int d = i * 64 + l;
        he[i] = (ent_w[hI * NDIM + d] - g_mean[d])            * g_rstd[d]            * bne_g[d] + bne_b[d];
        te[i] = (ent_w[tI * NDIM + d] - g_mean[NDIM + d])     * g_rstd[NDIM + d]     * bne_g[d] + bne_b[d];
        re[i] = (rel_w[rI * NDIM + d] - g_mean[2 * NDIM + d]) * g_rstd[2 * NDIM + d] * bnr_g[d] + bnr_b[d];
    }
    float hv[4] = {0.f, 0.f, 0.f, 0.f};
    float tv[4] = {0.f, 0.f, 0.f, 0.f};
#pragma unroll
    for (int i = 0; i < 4; i++) {
#pragma unroll
        for (int j = 0; j < 4; j++) {
            float rt = re[i] * te[j];
            float rh = re[i] * he[j];
#pragma unroll
            for (int k = 0; k < 4; k++) {
                hv[k] = fmaf(af[(i * 4 + j) * 4 + k], rt, hv[k]);   // alpha[i,j,k]
                tv[k] = fmaf(af[(i * 4 + k) * 4 + j], rh, tv[k]);   // alpha[i,k,j]
            }
        }
    }
#pragma unroll
    for (int k = 0; k < 4; k++) {
        g_vec[b * NDIM + k * 64 + l]            = hv[k];
        g_vec[(BATCH + b) * NDIM + k * 64 + l]  = tv[k];
    }
}

// ---------------- K3: label logits z_lab[row] = dot(vec[row], ent_w[label]) ----------------
// grid = 256 blocks, 256 threads (8 warps per block, one warp per row)
__global__ void k_zlab(const int* __restrict__ facts,
                       const float* __restrict__ ent_w) {
    int w    = threadIdx.x >> 5;
    int lane = threadIdx.x & 31;
    int rid  = blockIdx.x * 8 + w;            // 0..2047
    int m    = rid >> 10;                     // 0 -> head (label h), 1 -> tail (label t)
    int b    = rid & 1023;
    int lab  = facts[b * 3 + m];
    float s = 0.f;
    for (int d = lane; d < NDIM; d += 32)
        s = fmaf(g_vec[rid * NDIM + d], ent_w[lab * NDIM + d], s);
#pragma unroll
    for (int o = 16; o > 0; o >>= 1)
        s += __shfl_xor_sync(0xffffffffu, s, o);
    if (lane == 0) g_zlab[rid] = s;
}

// ---------------- K4: fused GEMM + exp-moment epilogue ----------------
// grid = (NCB, 16), 256 threads; 128x128 tile, 8x8 per thread, BK=8
__global__ __launch_bounds__(256, 2) void k_gemm(const float* __restrict__ ent_w) {
    __shared__ __align__(16) float sm[2048];   // As [8][128] | Bs [8][128]; reused as 16x128 red buffer
    float* As = sm;
    float* Bs = sm + 1024;

    int tid  = threadIdx.x;
    int cb   = blockIdx.x;
    int rb   = blockIdx.y;
    int row0 = rb * BM;
    int col0 = cb * BE;

    int lr = tid >> 1;            // 0..127 : tile row / entity row
    int lk = (tid & 1) * 4;       // 0 or 4 : k sub-offset
    const float* ag   = g_vec + (size_t)(row0 + lr) * NDIM + lk;
    bool         bval = (col0 + lr) < NENT;
    const float* bg   = ent_w + (size_t)(bval ? (col0 + lr) : 0) * NDIM + lk;

    int rm = tid >> 4;            // 0..15
    int rn = tid & 15;            // 0..15

    float acc[8][8];
#pragma unroll
    for (int i = 0; i < 8; i++)
#pragma unroll
        for (int j = 0; j < 8; j++) acc[i][j] = 0.f;

    for (int k0 = 0; k0 < NDIM; k0 += 8) {
        float4 av = *(const float4*)(ag + k0);
        float4 bv = bval ? *(const float4*)(bg + k0) : make_float4(0.f, 0.f, 0.f, 0.f);
        __syncthreads();
        As[(lk + 0) * 128 + lr] = av.x;
        As[(lk + 1) * 128 + lr] = av.y;
        As[(lk + 2) * 128 + lr] = av.z;
        As[(lk + 3) * 128 + lr] = av.w;
        Bs[(lk + 0) * 128 + lr] = bv.x;
        Bs[(lk + 1) * 128 + lr] = bv.y;
        Bs[(lk + 2) * 128 + lr] = bv.z;
        Bs[(lk + 3) * 128 + lr] = bv.w;
        __syncthreads();
#pragma unroll
        for (int k = 0; k < 8; k++) {
            float a[8], b[8];
            *(float4*)(a)     = *(const float4*)&As[k * 128 + rm * 8];
            *(float4*)(a + 4) = *(const float4*)&As[k * 128 + rm * 8 + 4];
            *(float4*)(b)     = *(const float4*)&Bs[k * 128 + rn * 8];
            *(float4*)(b + 4) = *(const float4*)&Bs[k * 128 + rn * 8 + 4];
#pragma unroll
            for (int i = 0; i < 8; i++)
#pragma unroll
                for (int j = 0; j < 8; j++)
                    acc[i][j] = fmaf(a[i], b[j], acc[i][j]);
        }
    }

    // Epilogue: per-row power sums S1..S4 over this entity tile (mask padded cols)
    float mom[8][4];
#pragma unroll
    for (int i = 0; i < 8; i++)
#pragma unroll
        for (int n = 0; n < 4; n++) mom[i][n] = 0.f;

#pragma unroll
    for (int i = 0; i < 8; i++) {
#pragma unroll
        for (int j = 0; j < 8; j++) {
            if (col0 + rn * 8 + j < NENT) {
                float e1 = __expf(acc[i][j]);
                float e2 = e1 * e1;
                mom[i][0] += e1;
                mom[i][1] += e2;
                mom[i][2] += e2 * e1;
                mom[i][3] += e2 * e2;
            }
        }
    }

    // Deterministic in-block reduce across rn (16 partials per row), then store
#pragma unroll
    for (int n = 0; n < 4; n++) {
        __syncthreads();
#pragma unroll
        for (int i = 0; i < 8; i++) sm[rn * 128 + rm * 8 + i] = mom[i][n];
        __syncthreads();
        if (tid < 128) {
            float s = 0.f;
#pragma unroll
            for (int q = 0; q < 16; q++) s += sm[q * 128 + tid];
            g_part[((size_t)(row0 + tid) * NCB + cb) * 4 + n] = s;
        }
    }
}

// ---------------- K5: per-row finalize (reduce partials, form BCE row total) ----------------
// grid = 2048 blocks, 128 threads
__global__ void k_fin() {
    int row = blockIdx.x;
    int tid = threadIdx.x;
    float s[4] = {0.f, 0.f, 0.f, 0.f};
    for (int cb = tid; cb < NCB; cb += 128) {
        const float* p = &g_part[((size_t)row * NCB + cb) * 4];
        s[0] += p[0]; s[1] += p[1]; s[2] += p[2]; s[3] += p[3];
    }
    __shared__ float red[512];
#pragma unroll
    for (int n = 0; n < 4; n++) red[n * 128 + tid] = s[n];
    __syncthreads();
    for (int o = 64; o > 0; o >>= 1) {
        if (tid < o) {
#pragma unroll
            for (int n = 0; n < 4; n++) red[n * 128 + tid] += red[n * 128 + tid + o];
        }
        __syncthreads();
    }
    if (tid == 0) {
        float S1 = red[0], S2 = red[128], S3 = red[256], S4 = red[384];
        float z  = g_zlab[row];
        float inv1 = 1.0f / S1;
        float inv2 = inv1 * inv1;
        float r2 = S2 * inv2;
        float r3 = S3 * inv2 * inv1;
        float r4 = S4 * inv2 * inv2;
        // sum_j log1p(-p_j) = -(S1/S1 + S2/2S1^2 + S3/3S1^3 + S4/4S1^4)
        float sum_log1mp = -(1.0f + 0.5f * r2 + (1.0f / 3.0f) * r3 + 0.25f * r4);
        float plab = __expf(z) * inv1;
        // row total = log p_lab + sum_{j != lab} log1p(-p_j)
        float T = (z - logf(S1)) + sum_log1mp - log1pf(-plab);
        g_rowtot[row] = T;
    }
}

// ---------------- K6: final scalar ----------------
__global__ void k_loss(float* __restrict__ out) {
    __shared__ float red[1024];
    int tid = threadIdx.x;
    red[tid] = g_rowtot[tid] + g_rowtot[tid + 1024];
    __syncthreads();
    for (int o = 512; o > 0; o >>= 1) {
        if (tid < o) red[tid] += red[tid + o];
        __syncthreads();
    }
    if (tid == 0) out[0] = -red[0] * (1.0f / ((float)BATCH * (float)NENT));
}

// ---------------- launch ----------------
extern "C" void kernel_launch(void* const* d_in, const int* in_sizes, int n_in,
                              void* d_out, int out_size) {
    const int*   facts = (const int*)d_in[0];
    const int*   arch  = (const int*)d_in[1];
    const float* ent_w = (const float*)d_in[2];
    const float* rel_w = (const float*)d_in[3];
    const float* bne_g = (const float*)d_in[4];
    const float* bne_b = (const float*)d_in[5];
    const float* bnr_g = (const float*)d_in[6];
    const float* bnr_b = (const float*)d_in[7];
    float* out = (float*)d_out;

    k_bn<<<3 * 256, 256>>>(facts, ent_w, rel_w);
    k_vec<<<BATCH, 64>>>(facts, ent_w, rel_w, bne_g, bne_b, bnr_g, bnr_b, arch);
    k_zlab<<<256, 256>>>(facts, ent_w);
    dim3 gg(NCB, 16);
    k_gemm<<<gg, 256>>>(ent_w);
    k_fin<<<ROWS, 128>>>();
    k_loss<<<1, 1024>>>(out);
}

// round 8
// speedup vs baseline: 3.3576x; 3.3576x over previous
#include <cuda_runtime.h>
#include <math.h>

// Problem constants
#define BATCH  1024
#define NDIM   256
#define NENT   50000
#define ROWS   2048              // 2 matrices (head/tail) x 1024 rows
#define BM     128               // GEMM row tile
#define BE     128               // GEMM entity tile
#define NCB    ((NENT + BE - 1) / BE)   // 391 column blocks
#define LDSM   36                // padded smem row stride (floats): banks 4q+p, conflict-free

// ---------------- device scratch (static: no allocation) ----------------
__device__ __align__(16) float g_mean[3 * NDIM];
__device__ __align__(16) float g_rstd[3 * NDIM];
__device__ __align__(16) float g_vec[ROWS * NDIM];        // 2 MB
__device__ float g_zlab[ROWS];
__device__ __align__(16) float g_part[(size_t)ROWS * NCB * 4];  // 12.8 MB moment partials
__device__ float g_rowtot[ROWS];

__device__ __forceinline__ unsigned f2tf32(float x) {
    unsigned u;
    asm("cvt.rna.tf32.f32 %0, %1;" : "=r"(u) : "f"(x));
    return u;
}

// ---------------- K1: batch-norm statistics ----------------
__global__ void k_bn(const int* __restrict__ facts,
                     const float* __restrict__ ent_w,
                     const float* __restrict__ rel_w) {
    int s = blockIdx.x >> 8;
    int d = blockIdx.x & 255;
    const float* tab = (s < 2) ? ent_w : rel_w;
    float sum = 0.f, sq = 0.f;
    for (int b = threadIdx.x; b < BATCH; b += 256) {
        int idx = facts[b * 3 + s];
        float x = tab[idx * NDIM + d];
        sum += x;
        sq  += x * x;
    }
    __shared__ float s1[256], s2[256];
    s1[threadIdx.x] = sum;
    s2[threadIdx.x] = sq;
    __syncthreads();
    for (int o = 128; o > 0; o >>= 1) {
        if (threadIdx.x < o) {
            s1[threadIdx.x] += s1[threadIdx.x + o];
            s2[threadIdx.x] += s2[threadIdx.x + o];
        }
        __syncthreads();
    }
    if (threadIdx.x == 0) {
        float m = s1[0] * (1.f / BATCH);
        float v = s2[0] * (1.f / BATCH) - m * m;
        g_mean[s * NDIM + d] = m;
        g_rstd[s * NDIM + d] = rsqrtf(v + 1e-5f);
    }
}

// ---------------- K2: alpha einsum -> head_vec / tail_vec ----------------
__global__ void k_vec(const int* __restrict__ facts,
                      const float* __restrict__ ent_w,
                      const float* __restrict__ rel_w,
                      const float* __restrict__ bne_g, const float* __restrict__ bne_b,
                      const float* __restrict__ bnr_g, const float* __restrict__ bnr_b,
                      const int* __restrict__ arch) {
    int b = blockIdx.x;
    int l = threadIdx.x;
    __shared__ float af[64];
    int a = arch[l];
    af[l] = (a == 0) ? 0.f : ((a == 1) ? 1.f : -1.f);
    __syncthreads();

    int hI = facts[b * 3 + 0];
    int tI = facts[b * 3 + 1];
    int rI = facts[b * 3 + 2];

    float re[4], te[4], he[4];
#pragma unroll
    for (int i = 0; i < 4; i++) {
        int d = i * 64 + l;
        he[i] = (ent_w[hI * NDIM + d] - g_mean[d])            * g_rstd[d]            * bne_g[d] + bne_b[d];
        te[i] = (ent_w[tI * NDIM + d] - g_mean[NDIM + d])     * g_rstd[NDIM + d]     * bne_g[d] + bne_b[d];
        re[i] = (rel_w[rI * NDIM + d] - g_mean[2 * NDIM + d]) * g_rstd[2 * NDIM + d] * bnr_g[d] + bnr_b[d];
    }
    float hv[4] = {0.f, 0.f, 0.f, 0.f};
    float tv[4] = {0.f, 0.f, 0.f, 0.f};
#pragma unroll
    for (int i = 0; i < 4; i++) {
#pragma unroll
        for (int j = 0; j < 4; j++) {
            float rt = re[i] * te[j];
            float rh = re[i] * he[j];
#pragma unroll
            for (int k = 0; k < 4; k++) {
                hv[k] = fmaf(af[(i * 4 + j) * 4 + k], rt, hv[k]);
                tv[k] = fmaf(af[(i * 4 + k) * 4 + j], rh, tv[k]);
            }
        }
    }
#pragma unroll
    for (int k = 0; k < 4; k++) {
        g_vec[b * NDIM + k * 64 + l]            = hv[k];
        g_vec[(BATCH + b) * NDIM + k * 64 + l]  = tv[k];
    }
}

// ---------------- K3: label logits (exact fp32) ----------------
__global__ void k_zlab(const int* __restrict__ facts,
                       const float* __restrict__ ent_w) {
    int w    = threadIdx.x >> 5;
    int lane = threadIdx.x & 31;
    int rid  = blockIdx.x * 8 + w;
    int m    = rid >> 10;
    int b    = rid & 1023;
    int lab  = facts[b * 3 + m];
    float s = 0.f;
    for (int d = lane; d < NDIM; d += 32)
        s = fmaf(g_vec[rid * NDIM + d], ent_w[lab * NDIM + d], s);
#pragma unroll
    for (int o = 16; o > 0; o >>= 1)
        s += __shfl_xor_sync(0xffffffffu, s, o);
    if (lane == 0) g_zlab[rid] = s;
}

// ---------------- K4: TF32 tensor-core GEMM + exp-moment epilogue ----------------
// grid = (NCB, 16), 256 threads (8 warps, 4m x 2n), CTA tile 128x128, BK=32
__global__ __launch_bounds__(256, 2) void k_gemm(const float* __restrict__ ent_w) {
    __shared__ unsigned As[BM * LDSM];   // 128 x 36 (padded), tf32 bits
    __shared__ unsigned Bs[BE * LDSM];

    int tid  = threadIdx.x;
    int cb   = blockIdx.x;
    int rb   = blockIdx.y;
    int row0 = rb * BM;
    int col0 = cb * BE;

    int warp = tid >> 5;
    int lane = tid & 31;
    int wm   = warp >> 1;      // 0..3 -> 32-row slab
    int wn   = warp & 1;       // 0..1 -> 64-col slab
    int q    = lane >> 2;      // 0..7
    int p    = lane & 3;       // 0..3

    int lrow = tid >> 3;       // 0..31  staging row (stepped by 32)
    int lk4  = tid & 7;        // float4 index within 32-wide chunk

    float acc[2][8][4];
#pragma unroll
    for (int i = 0; i < 2; i++)
#pragma unroll
        for (int j = 0; j < 8; j++)
#pragma unroll
            for (int c = 0; c < 4; c++) acc[i][j][c] = 0.f;

    for (int k0 = 0; k0 < NDIM; k0 += 32) {
        __syncthreads();
        // stage A (g_vec) and B (ent_w), converted to tf32
#pragma unroll
        for (int it = 0; it < 4; it++) {
            int r = lrow + it * 32;
            float4 va = *(const float4*)(g_vec + (size_t)(row0 + r) * NDIM + k0 + lk4 * 4);
            unsigned* da = &As[r * LDSM + lk4 * 4];
            da[0] = f2tf32(va.x); da[1] = f2tf32(va.y);
            da[2] = f2tf32(va.z); da[3] = f2tf32(va.w);

            int e = col0 + r;
            float4 vb = (e < NENT)
                ? *(const float4*)(ent_w + (size_t)e * NDIM + k0 + lk4 * 4)
                : make_float4(0.f, 0.f, 0.f, 0.f);
            unsigned* db = &Bs[r * LDSM + lk4 * 4];
            db[0] = f2tf32(vb.x); db[1] = f2tf32(vb.y);
            db[2] = f2tf32(vb.z); db[3] = f2tf32(vb.w);
        }
        __syncthreads();

#pragma unroll
        for (int ks = 0; ks < 4; ks++) {
            int kk = ks * 8 + p;
            unsigned a[2][4], b[8][2];
#pragma unroll
            for (int i = 0; i < 2; i++) {
                int rr = wm * 32 + i * 16 + q;
                a[i][0] = As[rr * LDSM + kk];
                a[i][1] = As[(rr + 8) * LDSM + kk];
                a[i][2] = As[rr * LDSM + kk + 4];
                a[i][3] = As[(rr + 8) * LDSM + kk + 4];
            }
#pragma unroll
            for (int j = 0; j < 8; j++) {
                int n = wn * 64 + j * 8 + q;
                b[j][0] = Bs[n * LDSM + kk];
                b[j][1] = Bs[n * LDSM + kk + 4];
            }
#pragma unroll
            for (int i = 0; i < 2; i++)
#pragma unroll
                for (int j = 0; j < 8; j++) {
                    asm volatile(
                        "mma.sync.aligned.m16n8k8.row.col.f32.tf32.tf32.f32 "
                        "{%0,%1,%2,%3}, {%4,%5,%6,%7}, {%8,%9}, {%0,%1,%2,%3};"
                        : "+f"(acc[i][j][0]), "+f"(acc[i][j][1]),
                          "+f"(acc[i][j][2]), "+f"(acc[i][j][3])
                        : "r"(a[i][0]), "r"(a[i][1]), "r"(a[i][2]), "r"(a[i][3]),
                          "r"(b[j][0]), "r"(b[j][1]));
                }
        }
    }

    // Epilogue: masked exp power-sums S1..S4 per row over this 128-entity tile.
    // mom[i][s][n]: i = m-tile, s = row half (0 -> q, 1 -> q+8)
    float mom[2][2][4];
#pragma unroll
    for (int i = 0; i < 2; i++)
#pragma unroll
        for (int s = 0; s < 2; s++)
#pragma unroll
            for (int n = 0; n < 4; n++) mom[i][s][n] = 0.f;

#pragma unroll
    for (int i = 0; i < 2; i++)
#pragma unroll
        for (int j = 0; j < 8; j++) {
            int cbase = col0 + wn * 64 + j * 8 + 2 * p;
#pragma unroll
            for (int s = 0; s < 2; s++)
#pragma unroll
                for (int u = 0; u < 2; u++) {
                    if (cbase + u < NENT) {
                        float e1 = __expf(acc[i][j][s * 2 + u]);
                        float e2 = e1 * e1;
                        mom[i][s][0] += e1;
                        mom[i][s][1] += e2;
                        mom[i][s][2] += e2 * e1;
                        mom[i][s][3] += e2 * e2;
                    }
                }
        }

    // quad reduce over p (lanes 4q+p share rows)
#pragma unroll
    for (int off = 1; off <= 2; off <<= 1)
#pragma unroll
        for (int i = 0; i < 2; i++)
#pragma unroll
            for (int s = 0; s < 2; s++)
#pragma unroll
                for (int n = 0; n < 4; n++)
                    mom[i][s][n] += __shfl_xor_sync(0xffffffffu, mom[i][s][n], off);

    // reduce across the 2 warp-columns through shared (reuse As)
    float* red = (float*)As;   // need 2*128*4 = 1024 floats
    __syncthreads();
    if (p == 0) {
#pragma unroll
        for (int i = 0; i < 2; i++)
#pragma unroll
            for (int s = 0; s < 2; s++) {
                int rl = wm * 32 + i * 16 + s * 8 + q;
                float4* dst = (float4*)&red[(wn * BM + rl) * 4];
                *dst = make_float4(mom[i][s][0], mom[i][s][1], mom[i][s][2], mom[i][s][3]);
            }
    }
    __syncthreads();
    if (tid < BM) {
        float4 u = *(float4*)&red[tid * 4];
        float4 v = *(float4*)&red[(BM + tid) * 4];
        float4 o = make_float4(u.x + v.x, u.y + v.y, u.z + v.z, u.w + v.w);
        *(float4*)&g_part[((size_t)(row0 + tid) * NCB + cb) * 4] = o;
    }
}

// ---------------- K5: per-row finalize ----------------
__global__ void k_fin() {
    int row = blockIdx.x;
    int tid = threadIdx.x;
    float s[4] = {0.f, 0.f, 0.f, 0.f};
    for (int cb = tid; cb < NCB; cb += 128) {
        const float* p = &g_part[((size_t)row * NCB + cb) * 4];
        s[0] += p[0]; s[1] += p[1]; s[2] += p[2]; s[3] += p[3];
    }
    __shared__ float red[512];
#pragma unroll
    for (int n = 0; n < 4; n++) red[n * 128 + tid] = s[n];
    __syncthreads();
    for (int o = 64; o > 0; o >>= 1) {
        if (tid < o) {
#pragma unroll
            for (int n = 0; n < 4; n++) red[n * 128 + tid] += red[n * 128 + tid + o];
        }
        __syncthreads();
    }
    if (tid == 0) {
        float S1 = red[0], S2 = red[128], S3 = red[256], S4 = red[384];
        float z  = g_zlab[row];
        float inv1 = 1.0f / S1;
        float inv2 = inv1 * inv1;
        float r2 = S2 * inv2;
        float r3 = S3 * inv2 * inv1;
        float r4 = S4 * inv2 * inv2;
        float sum_log1mp = -(1.0f + 0.5f * r2 + (1.0f / 3.0f) * r3 + 0.25f * r4);
        float plab = __expf(z) * inv1;
        float T = (z - logf(S1)) + sum_log1mp - log1pf(-plab);
        g_rowtot[row] = T;
    }
}

// ---------------- K6: final scalar ----------------
__global__ void k_loss(float* __restrict__ out) {
    __shared__ float red[1024];
    int tid = threadIdx.x;
    red[tid] = g_rowtot[tid] + g_rowtot[tid + 1024];
    __syncthreads();
    for (int o = 512; o > 0; o >>= 1) {
        if (tid < o) red[tid] += red[tid + o];
        __syncthreads();
    }
    if (tid == 0) out[0] = -red[0] * (1.0f / ((float)BATCH * (float)NENT));
}

// ---------------- launch ----------------
extern "C" void kernel_launch(void* const* d_in, const int* in_sizes, int n_in,
                              void* d_out, int out_size) {
    const int*   facts = (const int*)d_in[0];
    const int*   arch  = (const int*)d_in[1];
    const float* ent_w = (const float*)d_in[2];
    const float* rel_w = (const float*)d_in[3];
    const float* bne_g = (const float*)d_in[4];
    const float* bne_b = (const float*)d_in[5];
    const float* bnr_g = (const float*)d_in[6];
    const float* bnr_b = (const float*)d_in[7];
    float* out = (float*)d_out;

    k_bn<<<3 * 256, 256>>>(facts, ent_w, rel_w);
    k_vec<<<BATCH, 64>>>(facts, ent_w, rel_w, bne_g, bne_b, bnr_g, bnr_b, arch);
    k_zlab<<<256, 256>>>(facts, ent_w);
    dim3 gg(NCB, 16);
    k_gemm<<<gg, 256>>>(ent_w);
    k_fin<<<ROWS, 128>>>();
    k_loss<<<1, 1024>>>(out);
}